// round 13
// baseline (speedup 1.0000x reference)
#include <cuda_runtime.h>
#include <cuda_fp16.h>
#include <math.h>

#define cB 32
#define cS 145
#define cC 768
#define cD 8192
#define cSN 64
#define MPAD 160

__device__ float g_se1[cB*cC];
__device__ float g_a1[cB*cD];
__device__ float g_a2[cB*cD];
__device__ float g_u1[cD];
__device__ float g_u2[cD];
__device__ float g_q0[cB*cD];
__device__ float g_q1[cB*cD];
__device__ float g_q2[cD];
__device__ float g_A[3*cB*MPAD];
__device__ int   g_flag;
__device__ int   g_done;
__device__ __half g_x1h[cB*MPAD*cC];  // fp16 X1t, chunk-packed per 64-k block
__device__ float  g_x2[cB*MPAD*cC];   // exact X2t; pad rows stay 0

// ---------------- k_prep_se1: fused prep (y<145) + se1 (y==145) ------------
__global__ void k_prep_se1(const float* __restrict__ img, const float* __restrict__ tok,
                           const int* __restrict__ s1, const int* __restrict__ s2,
                           const float* __restrict__ sensor, const float* __restrict__ Wsen,
                           const float* __restrict__ bsen, const int* __restrict__ h1,
                           const int* __restrict__ h2, const float* __restrict__ b_s2)
{
    int b = blockIdx.x, y = blockIdx.y, tid = threadIdx.x;
    if (y < cS) {
        size_t o = (size_t)(b*MPAD + y)*cC;
        const float* ir = img + ((size_t)b*cS + y)*cC;
        for (int c = tid; c < cC; c += 256) {
            float f1 = (float)s1[c], f2 = (float)s2[c];
            float v = ir[c] + tok[cC + c];
            int g = (c >> 4) & 3, p = (c >> 1) & 7, par = c & 1;
            int chunk = (g >> 1)*4 + (p & 3);
            int sl = (g & 1)*2 + (p >> 2);
            int pos = (c & ~63) | (chunk*8 + sl*2 + par);
            g_x1h[o + pos] = __float2half_rn(v*f1);
            g_x2[o + c]    = v*f2;
        }
        return;
    }
    __shared__ float ss[cSN];
    __shared__ int sflag;
    for (int j = tid; j < cD; j += 256) { g_a1[b*cD + j] = 0.f; g_a2[b*cD + j] = 0.f; }
    if (b == 0) for (int j = tid; j < cD; j += 256) { g_u1[j] = 0.f; g_u2[j] = 0.f; }
    #pragma unroll
    for (int z = 0; z < 3; ++z)
        for (int j = tid; j < MPAD; j += 256) g_A[(z*cB + b)*MPAD + j] = 0.f;
    if (b == 0 && tid == 0) g_done = 0;

    if (tid == 0) sflag = 0;
    if (tid < cSN) ss[tid] = sensor[b*cSN + tid];
    __syncthreads();
    if (b == 0 && tid < cS && b_s2[tid] != 0.f) atomicOr(&sflag, 1);

    for (int c = tid; c < cC; c += 256) {
        float acc = bsen[c];
        const float* w = Wsen + c*cSN;
        #pragma unroll 16
        for (int n = 0; n < cSN; ++n) acc += ss[n]*w[n];
        g_se1[b*cC + c] = acc;
        float f1 = (float)s1[c], f2 = (float)s2[c];
        atomicAdd(&g_a1[b*cD + h1[c]], acc*f1);
        atomicAdd(&g_a2[b*cD + h2[c]], acc*f2);
        if (b == 0) { atomicAdd(&g_u1[h1[c]], f1); atomicAdd(&g_u2[h2[c]], f2); }
    }
    if (b == 0) {
        __syncthreads();
        if (tid == 0) g_flag = sflag;
    }
}

// ---------------- k_conv: half2-packed a1 + fused bias tail ----------------
#define CONV_SMEM (16384*4 + 768*8)   // 71680 B
__global__ __launch_bounds__(256) void k_conv(const int* __restrict__ h1,
                                              const int* __restrict__ h2,
                                              const int* __restrict__ s1,
                                              const int* __restrict__ s2)
{
    extern __shared__ float smc[];
    __half2* a1p = (__half2*)smc;
    float2*  pt  = (float2*)(smc + 16384);

    int b = blockIdx.x, tid = threadIdx.x;
    const float* ga = g_a1 + b*cD;
    for (int j = tid; j < 16384; j += 256) {
        float v0 = ga[j & (cD - 1)];
        float v1 = ga[(j + 512) & (cD - 1)];
        a1p[j] = __floats2half2_rn(v0, v1);
    }
    for (int c = tid; c < cC; c += 256) {
        float2 e;
        e.x = __int_as_float(cD - h2[c]);
        e.y = g_se1[b*cC + c]*(float)s2[c];
        pt[c] = e;
    }
    __syncthreads();

    int d0 = blockIdx.y*1024 + tid;
    int i1 = d0 + 256;
    float q00 = 0.f, q01 = 0.f, q10 = 0.f, q11 = 0.f;
    #pragma unroll 4
    for (int c = 0; c < cC; ++c) {
        float2 p = pt[c];
        int sh = __float_as_int(p.x);
        float2 va = __half22float2(a1p[d0 + sh]);
        float2 vb = __half22float2(a1p[i1 + sh]);
        q00 += p.y*va.x; q01 += p.y*va.y;
        q10 += p.y*vb.x; q11 += p.y*vb.y;
    }
    float* qo = g_q0 + b*cD;
    qo[d0]       = q00;
    qo[d0 + 512] = q01;
    qo[d0 + 256] = q10;
    qo[d0 + 768] = q11;

    // fused bias path (never taken in this dataset)
    if (g_flag) {
        __syncthreads();
        int*   psh2 = (int*)smc;
        int*   psh1 = psh2 + cC;
        float* ps1f = (float*)(psh1 + cC);
        float* ps2f = ps1f + cC;
        for (int c = tid; c < cC; c += 256) {
            psh2[c] = cD - h2[c]; psh1[c] = cD - h1[c];
            ps1f[c] = (float)s1[c]; ps2f[c] = (float)s2[c];
        }
        __syncthreads();
        const float* a1 = g_a1 + b*cD;
        const float* a2 = g_a2 + b*cD;
        int dbase = blockIdx.y*1024 + tid;
        for (int j = 0; j < 4; ++j) {
            int d = dbase + j*256;
            float q1 = 0.f, q2 = 0.f;
            for (int c = 0; c < cC; ++c) {
                int i2 = (d + psh2[c]) & (cD - 1);
                int iv = (d + psh1[c]) & (cD - 1);
                q1 += ps2f[c]*__ldg(a1 + i2) + ps1f[c]*__ldg(a2 + iv);
                q2 += ps2f[c]*__ldg(g_u1 + i2);
            }
            g_q1[b*cD + d] = q1;
            if (b == 0) g_q2[d] = q2;
        }
    }
}

// ---------------- k_quad: mma (y<12) + bias (y>=12) + fused final ----------
#define SQH_OFF  0
#define SH1_OFF  4096
#define SRED_OFF (SH1_OFF + 768)
#define SA_OFF   (SRED_OFF + 160)
#define SB_OFF   (SA_OFF + 5120)
#define SMEM_Q   (SB_OFF + 2048)         // 12192 floats = 48768 B
#define NBLK_Q   (cB*36)

#define MMA16(acc, a0, a1, a2, a3, b0, b1) \
    asm volatile( \
        "mma.sync.aligned.m16n8k16.row.col.f32.f16.f16.f32 " \
        "{%0,%1,%2,%3}, {%4,%5,%6,%7}, {%8,%9}, {%0,%1,%2,%3};" \
        : "+f"((acc)[0]), "+f"((acc)[1]), "+f"((acc)[2]), "+f"((acc)[3]) \
        : "r"(a0), "r"(a1), "r"(a2), "r"(a3), "r"(b0), "r"(b1))

__global__ __launch_bounds__(128, 4) void k_quad(const int* __restrict__ h1,
                                                 const int* __restrict__ h2,
                                                 const float* __restrict__ img,
                                                 const float* __restrict__ tok,
                                                 const int* __restrict__ s1,
                                                 const int* __restrict__ s2,
                                                 const float* __restrict__ W_s2,
                                                 const float* __restrict__ b_s2,
                                                 const float* __restrict__ W_out,
                                                 const float* __restrict__ b_out,
                                                 float* __restrict__ out)
{
    extern __shared__ float sm[];
    __shared__ int isLast;
    int b = blockIdx.x, y = blockIdx.y;
    int tid = threadIdx.x, lane = tid & 31, warp = tid >> 5;

    if (y < 12) {
        unsigned short* sQh = (unsigned short*)sm;
        int*   sH1L = (int*)(sm + SH1_OFF);
        float* sRed = sm + SRED_OFF;
        uint4* sAv  = (uint4*)(sm + SA_OFF);
        uint4* sBv  = (uint4*)(sm + SB_OFF);

        int c2base = y*64;
        int wm = warp & 1, wn = warp >> 1;
        int t4 = lane & 3, qr = lane >> 2;

        const float* qsrc = g_q0 + b*cD;
        for (int j = tid; j < cD; j += 128)
            sQh[j] = __half_as_ushort(__float2half_rn(qsrc[j]));
        for (int i = tid; i < cC; i += 128) {
            int pos = i & 63, blk = i & ~63;
            int c = pos >> 3, sl = (pos >> 1) & 3, par = pos & 1;
            int g = (c >> 2)*2 + (sl >> 1);
            int p = (c & 3) | ((sl & 1) << 2);
            sH1L[i] = h1[blk | (g*16 + p*2 + par)];
        }
        for (int j = tid; j < MPAD; j += 128) sRed[j] = 0.f;
        int gcol = tid >> 1, gP = tid & 1;
        int h2v = h2[c2base + gcol];
        __syncthreads();

        const __half* x1p = g_x1h + (size_t)b*MPAD*cC;

        float acc[5][4][4];
        #pragma unroll
        for (int mi = 0; mi < 5; ++mi)
            #pragma unroll
            for (int ni = 0; ni < 4; ++ni)
                #pragma unroll
                for (int j = 0; j < 4; ++j) acc[mi][ni][j] = 0.f;

        for (int r = 0; r < 12; ++r) {
            #pragma unroll
            for (int i = 0; i < 10; ++i) {
                int e = tid + i*128;
                int row = e >> 3, ch = e & 7;
                uint4 v = *(const uint4*)(x1p + (size_t)row*cC + r*64 + ch*8);
                sAv[row*8 + (ch ^ (row & 7))] = v;
            }
            {
                const int* hL = sH1L + r*64;
                int cb8 = gcol*8, cm = gcol & 7;
                #pragma unroll
                for (int cc = 0; cc < 4; ++cc) {
                    int c = gP*4 + cc;
                    unsigned u[4];
                    #pragma unroll
                    for (int sl = 0; sl < 4; ++sl) {
                        int pos = c*8 + sl*2;
                        unsigned lo = sQh[(hL[pos]     + h2v) & (cD - 1)];
                        unsigned hi = sQh[(hL[pos + 1] + h2v) & (cD - 1)];
                        u[sl] = lo | (hi << 16);
                    }
                    sBv[cb8 + (c ^ cm)] = make_uint4(u[0], u[1], u[2], u[3]);
                }
            }
            __syncthreads();

            #pragma unroll
            for (int P = 0; P < 2; ++P) {
                uint4 Bv[4];
                #pragma unroll
                for (int ni = 0; ni < 4; ++ni) {
                    int n0 = wn*32 + ni*8 + qr;
                    Bv[ni] = sBv[n0*8 + ((P*4 + t4) ^ qr)];
                }
                #pragma unroll
                for (int mi = 0; mi < 5; ++mi) {
                    int r0 = wm*80 + mi*16 + qr;
                    uint4 La = sAv[r0*8 + ((P*4 + t4) ^ qr)];
                    uint4 Lb = sAv[(r0 + 8)*8 + ((P*4 + t4) ^ qr)];
                    #pragma unroll
                    for (int ni = 0; ni < 4; ++ni) {
                        MMA16(acc[mi][ni], La.x, Lb.x, La.y, Lb.y, Bv[ni].x, Bv[ni].y);
                        MMA16(acc[mi][ni], La.z, Lb.z, La.w, Lb.w, Bv[ni].z, Bv[ni].w);
                    }
                }
            }
            __syncthreads();
        }

        const float* x2p = g_x2 + (size_t)b*MPAD*cC;
        #pragma unroll
        for (int mi = 0; mi < 5; ++mi) {
            int r0 = wm*80 + mi*16 + qr;
            int r1 = r0 + 8;
            float s0 = 0.f, s1v = 0.f;
            #pragma unroll
            for (int ni = 0; ni < 4; ++ni) {
                int col = c2base + wn*32 + ni*8 + 2*t4;
                float2 xa = *(const float2*)(x2p + (size_t)r0*cC + col);
                float2 xb = *(const float2*)(x2p + (size_t)r1*cC + col);
                s0  += acc[mi][ni][0]*xa.x + acc[mi][ni][1]*xa.y;
                s1v += acc[mi][ni][2]*xb.x + acc[mi][ni][3]*xb.y;
            }
            atomicAdd(&sRed[r0], s0);
            atomicAdd(&sRed[r1], s1v);
        }
        __syncthreads();
        for (int j = tid; j < MPAD; j += 128) atomicAdd(&g_A[b*MPAD + j], sRed[j]);
    } else if (g_flag) {
        // bias quad path (never taken in this dataset); simple & correct
        int z = 1 + (y - 12)/12;
        int c2base = ((y - 12) % 12)*64;
        const float* qg = (z == 1) ? (g_q1 + b*cD) : g_q2;
        for (int e = tid; e < cS*cC; e += 128) {
            int s = e/cC, c1 = e - s*cC;
            float x1v = (img[((size_t)b*cS + s)*cC + c1] + tok[cC + c1])*(float)s1[c1];
            float accv = 0.f;
            for (int j = 0; j < 64; ++j) {
                int c2 = c2base + j;
                float x2v = (img[((size_t)b*cS + s)*cC + c2] + tok[cC + c2])*(float)s2[c2];
                accv += __ldg(qg + ((h1[c1] + h2[c2]) & (cD - 1)))*x2v;
            }
            atomicAdd(&g_A[(z*cB + b)*MPAD + s], x1v*accv);
        }
    }

    // completion counter + fused final (last of the 1152 blocks)
    __syncthreads();
    if (tid == 0) {
        __threadfence();
        isLast = (atomicAdd(&g_done, 1) == NBLK_Q - 1);
    }
    __syncthreads();
    if (isLast) {
        for (int bb = warp*8; bb < warp*8 + 8; ++bb) {
            float bpv[5]; float ssum = 0.f;
            #pragma unroll
            for (int i = 0; i < 5; ++i) {
                int s = lane + 32*i;
                float bp = 0.f;
                if (s < cS) {
                    float w = W_s2[s], be = b_s2[s];
                    float ip = w*w*g_A[bb*MPAD + s]
                             + w*be*g_A[(cB + bb)*MPAD + s]
                             + be*be*g_A[(2*cB + bb)*MPAD + s];
                    float sg = (ip > 0.f) ? 1.f : ((ip < 0.f) ? -1.f : 0.f);
                    bp = sg*sqrtf(fabsf(ip) + 1e-5f);
                }
                bpv[i] = bp;
                ssum += bp*bp;
            }
            for (int o = 16; o > 0; o >>= 1) ssum += __shfl_xor_sync(0xffffffffu, ssum, o);
            float norm = fmaxf(sqrtf(ssum), 1e-12f);
            float accv = 0.f;
            #pragma unroll
            for (int i = 0; i < 5; ++i) {
                int s = lane + 32*i;
                if (s < cS) accv += bpv[i]*W_out[s];
            }
            for (int o = 16; o > 0; o >>= 1) accv += __shfl_xor_sync(0xffffffffu, accv, o);
            if (lane == 0) out[bb] = accv/norm + b_out[0];
        }
    }
}

extern "C" void kernel_launch(void* const* d_in, const int* in_sizes, int n_in,
                              void* d_out, int out_size)
{
    int base = (in_sizes[7] == 1) ? 8 : 7;
    const float* sensor = (const float*)d_in[0];
    const float* img    = (const float*)d_in[1];
    const int*   h1     = (const int*)  d_in[3];
    const int*   h2     = (const int*)  d_in[4];
    const int*   s1     = (const int*)  d_in[5];
    const int*   s2     = (const int*)  d_in[6];
    const float* Wsen   = (const float*)d_in[base+0];
    const float* bsen   = (const float*)d_in[base+1];
    const float* Ws2    = (const float*)d_in[base+2];
    const float* bs2    = (const float*)d_in[base+3];
    const float* Wout   = (const float*)d_in[base+4];
    const float* bout   = (const float*)d_in[base+5];
    const float* tok    = (const float*)d_in[base+6];
    float* out = (float*)d_out;

    static int cfg = 0;
    if (!cfg) {
        cudaFuncSetAttribute(k_conv, cudaFuncAttributeMaxDynamicSharedMemorySize, CONV_SMEM);
        cudaFuncSetAttribute(k_quad, cudaFuncAttributeMaxDynamicSharedMemorySize, SMEM_Q*4);
        cfg = 1;
    }

    k_prep_se1<<<dim3(cB, cS + 1), 256>>>(img, tok, s1, s2, sensor, Wsen, bsen, h1, h2, bs2);
    k_conv<<<dim3(cB, 8), 256, CONV_SMEM>>>(h1, h2, s1, s2);
    k_quad<<<dim3(cB, 36), 128, SMEM_Q*4>>>(h1, h2, img, tok, s1, s2,
                                            Ws2, bs2, Wout, bout, out);
}

// round 14
// speedup vs baseline: 1.0394x; 1.0394x over previous
#include <cuda_runtime.h>
#include <cuda_fp16.h>
#include <math.h>

#define cB 32
#define cS 145
#define cC 768
#define cD 8192
#define cSN 64
#define MPAD 160

__device__ float g_se1[cB*cC];
__device__ float g_a1[cB*cD];
__device__ float g_a2[cB*cD];
__device__ float g_u1[cD];
__device__ float g_u2[cD];
__device__ float g_q0[cB*cD];
__device__ float g_q1[cB*cD];
__device__ float g_q2[cD];
__device__ float g_A[3*cB*MPAD];
__device__ int   g_flag;
__device__ __half g_x1h[cB*MPAD*cC];  // fp16 X1t, chunk-packed per 64-k block
__device__ float  g_x2[cB*MPAD*cC];   // exact X2t; pad rows stay 0

// ---------------- k_prep_se1: fused prep (y<145) + se1 (y==145) ------------
// X1 chunk layout per 64-k block: pos = chunk*8 + sl*2 + (c&1).
// Pairs (c even, c+1) are adjacent -> one u32 store; x2 pair -> one float2.
__global__ void k_prep_se1(const float* __restrict__ img, const float* __restrict__ tok,
                           const int* __restrict__ s1, const int* __restrict__ s2,
                           const float* __restrict__ sensor, const float* __restrict__ Wsen,
                           const float* __restrict__ bsen, const int* __restrict__ h1,
                           const int* __restrict__ h2, const float* __restrict__ b_s2)
{
    int b = blockIdx.x, y = blockIdx.y, tid = threadIdx.x;
    if (y < cS) {
        size_t o = (size_t)(b*MPAD + y)*cC;
        const float* ir = img + ((size_t)b*cS + y)*cC;
        unsigned* x1u = (unsigned*)(g_x1h + o);
        float2*   x2v = (float2*)(g_x2 + o);
        for (int cp = tid; cp < cC/2; cp += 256) {
            int c = 2*cp;
            float2 iv = *(const float2*)(ir + c);
            float t0 = tok[cC + c], t1 = tok[cC + c + 1];
            float v0 = iv.x + t0, v1 = iv.y + t1;
            float f10 = (float)s1[c], f11 = (float)s1[c + 1];
            float f20 = (float)s2[c], f21 = (float)s2[c + 1];
            __half2 hh = __floats2half2_rn(v0*f10, v1*f11);
            int g = (c >> 4) & 3, p = (c >> 1) & 7;
            int chunk = (g >> 1)*4 + (p & 3);
            int sl = (g & 1)*2 + (p >> 2);
            int pos = (c & ~63) | (chunk*8 + sl*2);
            x1u[pos >> 1] = *reinterpret_cast<unsigned*>(&hh);
            x2v[cp] = make_float2(v0*f20, v1*f21);
        }
        return;
    }
    __shared__ float ss[cSN];
    __shared__ int sflag;
    for (int j = tid; j < cD; j += 256) { g_a1[b*cD + j] = 0.f; g_a2[b*cD + j] = 0.f; }
    if (b == 0) for (int j = tid; j < cD; j += 256) { g_u1[j] = 0.f; g_u2[j] = 0.f; }
    #pragma unroll
    for (int z = 0; z < 3; ++z)
        for (int j = tid; j < MPAD; j += 256) g_A[(z*cB + b)*MPAD + j] = 0.f;

    if (tid == 0) sflag = 0;
    if (tid < cSN) ss[tid] = sensor[b*cSN + tid];
    __syncthreads();
    if (b == 0 && tid < cS && b_s2[tid] != 0.f) atomicOr(&sflag, 1);

    for (int c = tid; c < cC; c += 256) {
        float acc = bsen[c];
        const float* w = Wsen + c*cSN;
        #pragma unroll 16
        for (int n = 0; n < cSN; ++n) acc += ss[n]*w[n];
        g_se1[b*cC + c] = acc;
        float f1 = (float)s1[c], f2 = (float)s2[c];
        atomicAdd(&g_a1[b*cD + h1[c]], acc*f1);
        atomicAdd(&g_a2[b*cD + h2[c]], acc*f2);
        if (b == 0) { atomicAdd(&g_u1[h1[c]], f1); atomicAdd(&g_u2[h2[c]], f2); }
    }
    if (b == 0) {
        __syncthreads();
        if (tid == 0) g_flag = sflag;
    }
}

// ---------------- k_conv: half2-packed a1, fp32 accumulation ---------------
#define CONV_SMEM (16384*4 + 768*8)   // 71680 B
__global__ __launch_bounds__(256) void k_conv(const int* __restrict__ h2,
                                              const int* __restrict__ s2)
{
    extern __shared__ float smc[];
    __half2* a1p = (__half2*)smc;
    float2*  pt  = (float2*)(smc + 16384);

    int b = blockIdx.x, tid = threadIdx.x;
    const float* ga = g_a1 + b*cD;
    for (int j = tid; j < 16384; j += 256) {
        float v0 = ga[j & (cD - 1)];
        float v1 = ga[(j + 512) & (cD - 1)];
        a1p[j] = __floats2half2_rn(v0, v1);
    }
    for (int c = tid; c < cC; c += 256) {
        float2 e;
        e.x = __int_as_float(cD - h2[c]);
        e.y = g_se1[b*cC + c]*(float)s2[c];
        pt[c] = e;
    }
    __syncthreads();

    int d0 = blockIdx.y*1024 + tid;
    int i1 = d0 + 256;
    float q00 = 0.f, q01 = 0.f, q10 = 0.f, q11 = 0.f;
    #pragma unroll 4
    for (int c = 0; c < cC; ++c) {
        float2 p = pt[c];
        int sh = __float_as_int(p.x);
        float2 va = __half22float2(a1p[d0 + sh]);
        float2 vb = __half22float2(a1p[i1 + sh]);
        q00 += p.y*va.x; q01 += p.y*va.y;
        q10 += p.y*vb.x; q11 += p.y*vb.y;
    }
    float* qo = g_q0 + b*cD;
    qo[d0]       = q00;
    qo[d0 + 512] = q01;
    qo[d0 + 256] = q10;
    qo[d0 + 768] = q11;
}

// ---------------- k_conv_bias: lite ----------------------------------------
__global__ __launch_bounds__(256) void k_conv_bias(const int* __restrict__ h1,
                                                   const int* __restrict__ h2,
                                                   const int* __restrict__ s1,
                                                   const int* __restrict__ s2)
{
    __shared__ int   psh2[cC], psh1[cC];
    __shared__ float ps1[cC], ps2[cC];
    if (g_flag == 0) return;
    int b = blockIdx.x, tid = threadIdx.x;
    for (int c = tid; c < cC; c += 256) {
        psh2[c] = cD - h2[c]; psh1[c] = cD - h1[c];
        ps1[c] = (float)s1[c]; ps2[c] = (float)s2[c];
    }
    __syncthreads();
    const float* a1 = g_a1 + b*cD;
    const float* a2 = g_a2 + b*cD;
    int dbase = blockIdx.y*1024 + tid;
    for (int j = 0; j < 4; ++j) {
        int d = dbase + j*256;
        float q1 = 0.f, q2 = 0.f;
        for (int c = 0; c < cC; ++c) {
            int i2 = (d + psh2[c]) & (cD - 1);
            int i1v = (d + psh1[c]) & (cD - 1);
            q1 += ps2[c]*__ldg(a1 + i2) + ps1[c]*__ldg(a2 + i1v);
            q2 += ps2[c]*__ldg(g_u1 + i2);
        }
        g_q1[b*cD + d] = q1;
        if (b == 0) g_q2[d] = q2;
    }
}

// ---------------- k_quad_mma: 4 warps, LDS.128 frags, XOR swizzle ----------
#define SQH_OFF  0                       // 4096 floats (8192 halves)
#define SH1_OFF  4096                    // 768 ints
#define SRED_OFF (SH1_OFF + 768)         // 160
#define SA_OFF   (SRED_OFF + 160)        // 1280 uint4
#define SB_OFF   (SA_OFF + 5120)         // 512 uint4
#define SMEM_Q   (SB_OFF + 2048)         // 12192 floats = 48768 B

#define MMA16(acc, a0, a1, a2, a3, b0, b1) \
    asm volatile( \
        "mma.sync.aligned.m16n8k16.row.col.f32.f16.f16.f32 " \
        "{%0,%1,%2,%3}, {%4,%5,%6,%7}, {%8,%9}, {%0,%1,%2,%3};" \
        : "+f"((acc)[0]), "+f"((acc)[1]), "+f"((acc)[2]), "+f"((acc)[3]) \
        : "r"(a0), "r"(a1), "r"(a2), "r"(a3), "r"(b0), "r"(b1))

__global__ __launch_bounds__(128) void k_quad_mma(const int* __restrict__ h1,
                                                  const int* __restrict__ h2)
{
    extern __shared__ float sm[];
    unsigned short* sQh = (unsigned short*)sm;
    int*   sH1L = (int*)(sm + SH1_OFF);
    float* sRed = sm + SRED_OFF;
    uint4* sAv  = (uint4*)(sm + SA_OFF);
    uint4* sBv  = (uint4*)(sm + SB_OFF);

    int b = blockIdx.x, c2base = blockIdx.y*64;
    int tid = threadIdx.x, lane = tid & 31, warp = tid >> 5;
    int wm = warp & 1, wn = warp >> 1;
    int t4 = lane & 3, qr = lane >> 2;

    const float* qsrc = g_q0 + b*cD;
    for (int j = tid; j < cD; j += 128)
        sQh[j] = __half_as_ushort(__float2half_rn(qsrc[j]));
    for (int i = tid; i < cC; i += 128) {
        int pos = i & 63, blk = i & ~63;
        int c = pos >> 3, sl = (pos >> 1) & 3, par = pos & 1;
        int g = (c >> 2)*2 + (sl >> 1);
        int p = (c & 3) | ((sl & 1) << 2);
        sH1L[i] = h1[blk | (g*16 + p*2 + par)];
    }
    for (int j = tid; j < MPAD; j += 128) sRed[j] = 0.f;
    int gcol = tid >> 1, gP = tid & 1;
    int h2v = h2[c2base + gcol];
    __syncthreads();

    const __half* x1p = g_x1h + (size_t)b*MPAD*cC;

    float acc[5][4][4];
    #pragma unroll
    for (int mi = 0; mi < 5; ++mi)
        #pragma unroll
        for (int ni = 0; ni < 4; ++ni)
            #pragma unroll
            for (int j = 0; j < 4; ++j) acc[mi][ni][j] = 0.f;

    for (int r = 0; r < 12; ++r) {
        #pragma unroll
        for (int i = 0; i < 10; ++i) {
            int e = tid + i*128;
            int row = e >> 3, ch = e & 7;
            uint4 v = *(const uint4*)(x1p + (size_t)row*cC + r*64 + ch*8);
            sAv[row*8 + (ch ^ (row & 7))] = v;
        }
        {
            const int* hL = sH1L + r*64;
            int cb8 = gcol*8, cm = gcol & 7;
            #pragma unroll
            for (int cc = 0; cc < 4; ++cc) {
                int c = gP*4 + cc;
                unsigned u[4];
                #pragma unroll
                for (int sl = 0; sl < 4; ++sl) {
                    int pos = c*8 + sl*2;
                    unsigned lo = sQh[(hL[pos]     + h2v) & (cD - 1)];
                    unsigned hi = sQh[(hL[pos + 1] + h2v) & (cD - 1)];
                    u[sl] = lo | (hi << 16);
                }
                sBv[cb8 + (c ^ cm)] = make_uint4(u[0], u[1], u[2], u[3]);
            }
        }
        __syncthreads();

        #pragma unroll
        for (int P = 0; P < 2; ++P) {
            uint4 Bv[4];
            #pragma unroll
            for (int ni = 0; ni < 4; ++ni) {
                int n0 = wn*32 + ni*8 + qr;
                Bv[ni] = sBv[n0*8 + ((P*4 + t4) ^ qr)];
            }
            #pragma unroll
            for (int mi = 0; mi < 5; ++mi) {
                int r0 = wm*80 + mi*16 + qr;
                uint4 La = sAv[r0*8 + ((P*4 + t4) ^ qr)];
                uint4 Lb = sAv[(r0 + 8)*8 + ((P*4 + t4) ^ qr)];
                #pragma unroll
                for (int ni = 0; ni < 4; ++ni) {
                    MMA16(acc[mi][ni], La.x, Lb.x, La.y, Lb.y, Bv[ni].x, Bv[ni].y);
                    MMA16(acc[mi][ni], La.z, Lb.z, La.w, Lb.w, Bv[ni].z, Bv[ni].w);
                }
            }
        }
        __syncthreads();
    }

    const float* x2p = g_x2 + (size_t)b*MPAD*cC;
    #pragma unroll
    for (int mi = 0; mi < 5; ++mi) {
        int r0 = wm*80 + mi*16 + qr;
        int r1 = r0 + 8;
        float s0 = 0.f, s1v = 0.f;
        #pragma unroll
        for (int ni = 0; ni < 4; ++ni) {
            int col = c2base + wn*32 + ni*8 + 2*t4;
            float2 xa = *(const float2*)(x2p + (size_t)r0*cC + col);
            float2 xb = *(const float2*)(x2p + (size_t)r1*cC + col);
            s0  += acc[mi][ni][0]*xa.x + acc[mi][ni][1]*xa.y;
            s1v += acc[mi][ni][2]*xb.x + acc[mi][ni][3]*xb.y;
        }
        atomicAdd(&sRed[r0], s0);
        atomicAdd(&sRed[r1], s1v);
    }
    __syncthreads();
    for (int j = tid; j < MPAD; j += 128) atomicAdd(&g_A[b*MPAD + j], sRed[j]);
}

// ---------------- k_quad_bias: lite ----------------------------------------
__global__ __launch_bounds__(256) void k_quad_bias(const float* __restrict__ img,
                                                   const int* __restrict__ h1,
                                                   const int* __restrict__ h2,
                                                   const float* __restrict__ tok,
                                                   const int* __restrict__ s1,
                                                   const int* __restrict__ s2)
{
    __shared__ float sX1[32*161];
    __shared__ int   sH1[cC];
    __shared__ float sS1[cC], sS2[cC], sTk[cC];

    if (g_flag == 0) return;
    int z = blockIdx.z + 1;
    int b = blockIdx.x, c2base = blockIdx.y*64;
    int tx = threadIdx.x & 15, ty = threadIdx.x >> 4, tid = threadIdx.x;

    const float* qg = (z == 1) ? (g_q1 + b*cD) : g_q2;
    for (int j = tid; j < cC; j += 256) {
        sH1[j] = h1[j];
        sS1[j] = (float)s1[j]; sS2[j] = (float)s2[j];
        sTk[j] = tok[cC + j];
    }
    __syncthreads();

    int h2r[4];
    #pragma unroll
    for (int n = 0; n < 4; ++n) h2r[n] = h2[c2base + tx + 16*n];

    float acc[10][4];
    #pragma unroll
    for (int m = 0; m < 10; ++m)
        #pragma unroll
        for (int n = 0; n < 4; ++n) acc[m][n] = 0.f;

    for (int k0 = 0; k0 < cC; k0 += 32) {
        __syncthreads();
        #pragma unroll
        for (int i = 0; i < 20; ++i) {
            int e = tid + i*256;
            int kt = e & 31, s = e >> 5;
            int c1 = k0 + kt;
            float v = 0.f;
            if (s < cS) v = (img[(b*cS + s)*cC + c1] + sTk[c1])*sS1[c1];
            sX1[kt*161 + s] = v;
        }
        __syncthreads();
        for (int kt = 0; kt < 32; ++kt) {
            int h1v = sH1[k0 + kt];
            float x1r[10];
            #pragma unroll
            for (int m = 0; m < 10; ++m) x1r[m] = sX1[kt*161 + ty + 16*m];
            float qv[4];
            #pragma unroll
            for (int n = 0; n < 4; ++n) qv[n] = __ldg(qg + ((h1v + h2r[n]) & (cD - 1)));
            #pragma unroll
            for (int m = 0; m < 10; ++m)
                #pragma unroll
                for (int n = 0; n < 4; ++n)
                    acc[m][n] += x1r[m]*qv[n];
        }
    }

    #pragma unroll
    for (int m = 0; m < 10; ++m) {
        int s = ty + 16*m;
        if (s >= cS) continue;
        float al = 0.f;
        #pragma unroll
        for (int n = 0; n < 4; ++n) {
            int c2 = c2base + tx + 16*n;
            float x2v = (img[(b*cS + s)*cC + c2] + sTk[c2])*sS2[c2];
            al += acc[m][n]*x2v;
        }
        atomicAdd(&g_A[(z*cB + b)*MPAD + s], al);
    }
}

// ---------------- k_final --------------------------------------------------
__global__ void k_final(const float* __restrict__ W_s2, const float* __restrict__ b_s2,
                        const float* __restrict__ W_out, const float* __restrict__ b_out,
                        float* __restrict__ out)
{
    int tid = threadIdx.x;
    int b = tid >> 5, lane = tid & 31;
    float bpv[5]; float ssum = 0.f;
    #pragma unroll
    for (int i = 0; i < 5; ++i) {
        int s = lane + 32*i;
        float bp = 0.f;
        if (s < cS) {
            float w = W_s2[s], be = b_s2[s];
            float ip = w*w*g_A[b*MPAD + s]
                     + w*be*g_A[(cB + b)*MPAD + s]
                     + be*be*g_A[(2*cB + b)*MPAD + s];
            float sg = (ip > 0.f) ? 1.f : ((ip < 0.f) ? -1.f : 0.f);
            bp = sg*sqrtf(fabsf(ip) + 1e-5f);
        }
        bpv[i] = bp;
        ssum += bp*bp;
    }
    for (int o = 16; o > 0; o >>= 1) ssum += __shfl_xor_sync(0xffffffffu, ssum, o);
    float norm = fmaxf(sqrtf(ssum), 1e-12f);
    float acc = 0.f;
    #pragma unroll
    for (int i = 0; i < 5; ++i) {
        int s = lane + 32*i;
        if (s < cS) acc += bpv[i]*W_out[s];
    }
    for (int o = 16; o > 0; o >>= 1) acc += __shfl_xor_sync(0xffffffffu, acc, o);
    if (lane == 0) out[b] = acc/norm + b_out[0];
}

extern "C" void kernel_launch(void* const* d_in, const int* in_sizes, int n_in,
                              void* d_out, int out_size)
{
    int base = (in_sizes[7] == 1) ? 8 : 7;
    const float* sensor = (const float*)d_in[0];
    const float* img    = (const float*)d_in[1];
    const int*   h1     = (const int*)  d_in[3];
    const int*   h2     = (const int*)  d_in[4];
    const int*   s1     = (const int*)  d_in[5];
    const int*   s2     = (const int*)  d_in[6];
    const float* Wsen   = (const float*)d_in[base+0];
    const float* bsen   = (const float*)d_in[base+1];
    const float* Ws2    = (const float*)d_in[base+2];
    const float* bs2    = (const float*)d_in[base+3];
    const float* Wout   = (const float*)d_in[base+4];
    const float* bout   = (const float*)d_in[base+5];
    const float* tok    = (const float*)d_in[base+6];
    float* out = (float*)d_out;

    static int cfg = 0;
    if (!cfg) {
        cudaFuncSetAttribute(k_conv,     cudaFuncAttributeMaxDynamicSharedMemorySize, CONV_SMEM);
        cudaFuncSetAttribute(k_quad_mma, cudaFuncAttributeMaxDynamicSharedMemorySize, SMEM_Q*4);
        cfg = 1;
    }

    k_prep_se1<<<dim3(cB, cS + 1), 256>>>(img, tok, s1, s2, sensor, Wsen, bsen, h1, h2, bs2);
    k_conv<<<dim3(cB, 8), 256, CONV_SMEM>>>(h2, s2);
    k_conv_bias<<<dim3(cB, 8), 256>>>(h1, h2, s1, s2);
    k_quad_mma<<<dim3(cB, 12), 128, SMEM_Q*4>>>(h1, h2);
    k_quad_bias<<<dim3(cB, 12, 2), 256>>>(img, h1, h2, tok, s1, s2);
    k_final<<<1, 1024>>>(Ws2, bs2, Wout, bout, out);
}

// round 15
// speedup vs baseline: 1.0487x; 1.0089x over previous
#include <cuda_runtime.h>
#include <cuda_fp16.h>
#include <math.h>

#define cB 32
#define cS 145
#define cC 768
#define cD 8192
#define cSN 64
#define MPAD 160

__device__ float g_se1[cB*cC];
__device__ float g_a1[cB*cD];
__device__ float g_a2[cB*cD];
__device__ float g_u1[cD];
__device__ float g_u2[cD];
__device__ float g_q0[cB*cD];
__device__ float g_q1[cB*cD];
__device__ float g_q2[cD];
__device__ float g_A[3*cB*MPAD];
__device__ int   g_flag;
__device__ __half g_x1h[cB*MPAD*cC];  // fp16 X1t, chunk-packed; pad rows stay 0

// ---------------- k_prep_se1: fused prep (y<145) + se1 (y==145) ------------
// X1 only; X2 is recomputed in the quad epilogue directly from img.
__global__ void k_prep_se1(const float* __restrict__ img, const float* __restrict__ tok,
                           const int* __restrict__ s1, const int* __restrict__ s2,
                           const float* __restrict__ sensor, const float* __restrict__ Wsen,
                           const float* __restrict__ bsen, const int* __restrict__ h1,
                           const int* __restrict__ h2, const float* __restrict__ b_s2)
{
    int b = blockIdx.x, y = blockIdx.y, tid = threadIdx.x;
    if (y < cS) {
        size_t o = (size_t)(b*MPAD + y)*cC;
        const float* ir = img + ((size_t)b*cS + y)*cC;
        unsigned* x1u = (unsigned*)(g_x1h + o);
        for (int cp = tid; cp < cC/2; cp += 256) {
            int c = 2*cp;
            float2 iv = *(const float2*)(ir + c);
            float v0 = iv.x + tok[cC + c], v1 = iv.y + tok[cC + c + 1];
            float f10 = (float)s1[c], f11 = (float)s1[c + 1];
            __half2 hh = __floats2half2_rn(v0*f10, v1*f11);
            int g = (c >> 4) & 3, p = (c >> 1) & 7;
            int chunk = (g >> 1)*4 + (p & 3);
            int sl = (g & 1)*2 + (p >> 2);
            int pos = (c & ~63) | (chunk*8 + sl*2);
            x1u[pos >> 1] = *reinterpret_cast<unsigned*>(&hh);
        }
        return;
    }
    __shared__ float ss[cSN];
    __shared__ int sflag;
    for (int j = tid; j < cD; j += 256) { g_a1[b*cD + j] = 0.f; g_a2[b*cD + j] = 0.f; }
    if (b == 0) for (int j = tid; j < cD; j += 256) { g_u1[j] = 0.f; g_u2[j] = 0.f; }
    #pragma unroll
    for (int z = 0; z < 3; ++z)
        for (int j = tid; j < MPAD; j += 256) g_A[(z*cB + b)*MPAD + j] = 0.f;

    if (tid == 0) sflag = 0;
    if (tid < cSN) ss[tid] = sensor[b*cSN + tid];
    __syncthreads();
    if (b == 0 && tid < cS && b_s2[tid] != 0.f) atomicOr(&sflag, 1);

    for (int c = tid; c < cC; c += 256) {
        float acc = bsen[c];
        const float* w = Wsen + c*cSN;
        #pragma unroll 16
        for (int n = 0; n < cSN; ++n) acc += ss[n]*w[n];
        g_se1[b*cC + c] = acc;
        float f1 = (float)s1[c], f2 = (float)s2[c];
        atomicAdd(&g_a1[b*cD + h1[c]], acc*f1);
        atomicAdd(&g_a2[b*cD + h2[c]], acc*f2);
        if (b == 0) { atomicAdd(&g_u1[h1[c]], f1); atomicAdd(&g_u2[h2[c]], f2); }
    }
    if (b == 0) {
        __syncthreads();
        if (tid == 0) g_flag = sflag;
    }
}

// ---------------- k_conv: half2-packed a1, fp32 accumulation ---------------
#define CONV_SMEM (16384*4 + 768*8)   // 71680 B
__global__ __launch_bounds__(256) void k_conv(const int* __restrict__ h2,
                                              const int* __restrict__ s2)
{
    extern __shared__ float smc[];
    __half2* a1p = (__half2*)smc;
    float2*  pt  = (float2*)(smc + 16384);

    int b = blockIdx.x, tid = threadIdx.x;
    const float* ga = g_a1 + b*cD;
    for (int j = tid; j < 16384; j += 256) {
        float v0 = ga[j & (cD - 1)];
        float v1 = ga[(j + 512) & (cD - 1)];
        a1p[j] = __floats2half2_rn(v0, v1);
    }
    for (int c = tid; c < cC; c += 256) {
        float2 e;
        e.x = __int_as_float(cD - h2[c]);
        e.y = g_se1[b*cC + c]*(float)s2[c];
        pt[c] = e;
    }
    __syncthreads();

    int d0 = blockIdx.y*1024 + tid;
    int i1 = d0 + 256;
    float q00 = 0.f, q01 = 0.f, q10 = 0.f, q11 = 0.f;
    #pragma unroll 4
    for (int c = 0; c < cC; ++c) {
        float2 p = pt[c];
        int sh = __float_as_int(p.x);
        float2 va = __half22float2(a1p[d0 + sh]);
        float2 vb = __half22float2(a1p[i1 + sh]);
        q00 += p.y*va.x; q01 += p.y*va.y;
        q10 += p.y*vb.x; q11 += p.y*vb.y;
    }
    float* qo = g_q0 + b*cD;
    qo[d0]       = q00;
    qo[d0 + 512] = q01;
    qo[d0 + 256] = q10;
    qo[d0 + 768] = q11;
}

// ---------------- k_conv_bias: lite ----------------------------------------
__global__ __launch_bounds__(256) void k_conv_bias(const int* __restrict__ h1,
                                                   const int* __restrict__ h2,
                                                   const int* __restrict__ s1,
                                                   const int* __restrict__ s2)
{
    __shared__ int   psh2[cC], psh1[cC];
    __shared__ float ps1[cC], ps2[cC];
    if (g_flag == 0) return;
    int b = blockIdx.x, tid = threadIdx.x;
    for (int c = tid; c < cC; c += 256) {
        psh2[c] = cD - h2[c]; psh1[c] = cD - h1[c];
        ps1[c] = (float)s1[c]; ps2[c] = (float)s2[c];
    }
    __syncthreads();
    const float* a1 = g_a1 + b*cD;
    const float* a2 = g_a2 + b*cD;
    int dbase = blockIdx.y*1024 + tid;
    for (int j = 0; j < 4; ++j) {
        int d = dbase + j*256;
        float q1 = 0.f, q2 = 0.f;
        for (int c = 0; c < cC; ++c) {
            int i2 = (d + psh2[c]) & (cD - 1);
            int i1v = (d + psh1[c]) & (cD - 1);
            q1 += ps2[c]*__ldg(a1 + i2) + ps1[c]*__ldg(a2 + i1v);
            q2 += ps2[c]*__ldg(g_u1 + i2);
        }
        g_q1[b*cD + d] = q1;
        if (b == 0) g_q2[d] = q2;
    }
}

// ---------------- k_quad_mma: 4 warps, LDS.128 frags, XOR swizzle ----------
#define SQH_OFF  0                       // 4096 floats (8192 halves)
#define SH1_OFF  4096                    // 768 ints
#define SRED_OFF (SH1_OFF + 768)         // 160
#define SX2_OFF  (SRED_OFF + 160)        // 128 (s2f[64] | tok[64])
#define SA_OFF   (SX2_OFF + 128)         // 1280 uint4
#define SB_OFF   (SA_OFF + 5120)         // 512 uint4
#define SMEM_Q   (SB_OFF + 2048)         // 12320 floats = 49280 B

#define MMA16(acc, a0, a1, a2, a3, b0, b1) \
    asm volatile( \
        "mma.sync.aligned.m16n8k16.row.col.f32.f16.f16.f32 " \
        "{%0,%1,%2,%3}, {%4,%5,%6,%7}, {%8,%9}, {%0,%1,%2,%3};" \
        : "+f"((acc)[0]), "+f"((acc)[1]), "+f"((acc)[2]), "+f"((acc)[3]) \
        : "r"(a0), "r"(a1), "r"(a2), "r"(a3), "r"(b0), "r"(b1))

__global__ __launch_bounds__(128) void k_quad_mma(const int* __restrict__ h1,
                                                  const int* __restrict__ h2,
                                                  const float* __restrict__ img,
                                                  const float* __restrict__ tok,
                                                  const int* __restrict__ s2)
{
    extern __shared__ float sm[];
    unsigned short* sQh = (unsigned short*)sm;
    int*   sH1L = (int*)(sm + SH1_OFF);
    float* sRed = sm + SRED_OFF;
    float* sS2v = sm + SX2_OFF;          // 64
    float* sTkv = sm + SX2_OFF + 64;     // 64
    uint4* sAv  = (uint4*)(sm + SA_OFF);
    uint4* sBv  = (uint4*)(sm + SB_OFF);

    int b = blockIdx.x, c2base = blockIdx.y*64;
    int tid = threadIdx.x, lane = tid & 31, warp = tid >> 5;
    int wm = warp & 1, wn = warp >> 1;
    int t4 = lane & 3, qr = lane >> 2;

    const float* qsrc = g_q0 + b*cD;
    for (int j = tid; j < cD; j += 128)
        sQh[j] = __half_as_ushort(__float2half_rn(qsrc[j]));
    for (int i = tid; i < cC; i += 128) {
        int pos = i & 63, blk = i & ~63;
        int c = pos >> 3, sl = (pos >> 1) & 3, par = pos & 1;
        int g = (c >> 2)*2 + (sl >> 1);
        int p = (c & 3) | ((sl & 1) << 2);
        sH1L[i] = h1[blk | (g*16 + p*2 + par)];
    }
    for (int j = tid; j < MPAD; j += 128) sRed[j] = 0.f;
    if (tid < 64) {
        sS2v[tid] = (float)s2[c2base + tid];
        sTkv[tid] = tok[cC + c2base + tid];
    }
    int gcol = tid >> 1, gP = tid & 1;
    int h2v = h2[c2base + gcol];
    __syncthreads();

    const __half* x1p = g_x1h + (size_t)b*MPAD*cC;

    float acc[5][4][4];
    #pragma unroll
    for (int mi = 0; mi < 5; ++mi)
        #pragma unroll
        for (int ni = 0; ni < 4; ++ni)
            #pragma unroll
            for (int j = 0; j < 4; ++j) acc[mi][ni][j] = 0.f;

    for (int r = 0; r < 12; ++r) {
        #pragma unroll
        for (int i = 0; i < 10; ++i) {
            int e = tid + i*128;
            int row = e >> 3, ch = e & 7;
            uint4 v = *(const uint4*)(x1p + (size_t)row*cC + r*64 + ch*8);
            sAv[row*8 + (ch ^ (row & 7))] = v;
        }
        {
            const int* hL = sH1L + r*64;
            int cb8 = gcol*8, cm = gcol & 7;
            #pragma unroll
            for (int cc = 0; cc < 4; ++cc) {
                int c = gP*4 + cc;
                unsigned u[4];
                #pragma unroll
                for (int sl = 0; sl < 4; ++sl) {
                    int pos = c*8 + sl*2;
                    unsigned lo = sQh[(hL[pos]     + h2v) & (cD - 1)];
                    unsigned hi = sQh[(hL[pos + 1] + h2v) & (cD - 1)];
                    u[sl] = lo | (hi << 16);
                }
                sBv[cb8 + (c ^ cm)] = make_uint4(u[0], u[1], u[2], u[3]);
            }
        }
        __syncthreads();

        #pragma unroll
        for (int P = 0; P < 2; ++P) {
            uint4 Bv[4];
            #pragma unroll
            for (int ni = 0; ni < 4; ++ni) {
                int n0 = wn*32 + ni*8 + qr;
                Bv[ni] = sBv[n0*8 + ((P*4 + t4) ^ qr)];
            }
            #pragma unroll
            for (int mi = 0; mi < 5; ++mi) {
                int r0 = wm*80 + mi*16 + qr;
                uint4 La = sAv[r0*8 + ((P*4 + t4) ^ qr)];
                uint4 Lb = sAv[(r0 + 8)*8 + ((P*4 + t4) ^ qr)];
                #pragma unroll
                for (int ni = 0; ni < 4; ++ni) {
                    MMA16(acc[mi][ni], La.x, Lb.x, La.y, Lb.y, Bv[ni].x, Bv[ni].y);
                    MMA16(acc[mi][ni], La.z, Lb.z, La.w, Lb.w, Bv[ni].z, Bv[ni].w);
                }
            }
        }
        __syncthreads();
    }

    // epilogue: X2 recomputed from img (exact fp32, zero for pad rows)
    const float* imb = img + (size_t)b*cS*cC;
    #pragma unroll
    for (int mi = 0; mi < 5; ++mi) {
        int r0 = wm*80 + mi*16 + qr;
        int r1 = r0 + 8;
        float s0 = 0.f, s1v = 0.f;
        #pragma unroll
        for (int ni = 0; ni < 4; ++ni) {
            int l = wn*32 + ni*8 + 2*t4;
            int col = c2base + l;
            float2 sf = make_float2(sS2v[l], sS2v[l + 1]);
            float2 tk = make_float2(sTkv[l], sTkv[l + 1]);
            if (r0 < cS) {
                float2 ia = *(const float2*)(imb + (size_t)r0*cC + col);
                s0 += acc[mi][ni][0]*((ia.x + tk.x)*sf.x)
                    + acc[mi][ni][1]*((ia.y + tk.y)*sf.y);
            }
            if (r1 < cS) {
                float2 ib = *(const float2*)(imb + (size_t)r1*cC + col);
                s1v += acc[mi][ni][2]*((ib.x + tk.x)*sf.x)
                     + acc[mi][ni][3]*((ib.y + tk.y)*sf.y);
            }
        }
        atomicAdd(&sRed[r0], s0);
        atomicAdd(&sRed[r1], s1v);
    }
    __syncthreads();
    for (int j = tid; j < MPAD; j += 128) atomicAdd(&g_A[b*MPAD + j], sRed[j]);
}

// ---------------- k_quad_bias: lite ----------------------------------------
__global__ __launch_bounds__(256) void k_quad_bias(const float* __restrict__ img,
                                                   const int* __restrict__ h1,
                                                   const int* __restrict__ h2,
                                                   const float* __restrict__ tok,
                                                   const int* __restrict__ s1,
                                                   const int* __restrict__ s2)
{
    __shared__ float sX1[32*161];
    __shared__ int   sH1[cC];
    __shared__ float sS1[cC], sS2[cC], sTk[cC];

    if (g_flag == 0) return;
    int z = blockIdx.z + 1;
    int b = blockIdx.x, c2base = blockIdx.y*64;
    int tx = threadIdx.x & 15, ty = threadIdx.x >> 4, tid = threadIdx.x;

    const float* qg = (z == 1) ? (g_q1 + b*cD) : g_q2;
    for (int j = tid; j < cC; j += 256) {
        sH1[j] = h1[j];
        sS1[j] = (float)s1[j]; sS2[j] = (float)s2[j];
        sTk[j] = tok[cC + j];
    }
    __syncthreads();

    int h2r[4];
    #pragma unroll
    for (int n = 0; n < 4; ++n) h2r[n] = h2[c2base + tx + 16*n];

    float acc[10][4];
    #pragma unroll
    for (int m = 0; m < 10; ++m)
        #pragma unroll
        for (int n = 0; n < 4; ++n) acc[m][n] = 0.f;

    for (int k0 = 0; k0 < cC; k0 += 32) {
        __syncthreads();
        #pragma unroll
        for (int i = 0; i < 20; ++i) {
            int e = tid + i*256;
            int kt = e & 31, s = e >> 5;
            int c1 = k0 + kt;
            float v = 0.f;
            if (s < cS) v = (img[(b*cS + s)*cC + c1] + sTk[c1])*sS1[c1];
            sX1[kt*161 + s] = v;
        }
        __syncthreads();
        for (int kt = 0; kt < 32; ++kt) {
            int h1v = sH1[k0 + kt];
            float x1r[10];
            #pragma unroll
            for (int m = 0; m < 10; ++m) x1r[m] = sX1[kt*161 + ty + 16*m];
            float qv[4];
            #pragma unroll
            for (int n = 0; n < 4; ++n) qv[n] = __ldg(qg + ((h1v + h2r[n]) & (cD - 1)));
            #pragma unroll
            for (int m = 0; m < 10; ++m)
                #pragma unroll
                for (int n = 0; n < 4; ++n)
                    acc[m][n] += x1r[m]*qv[n];
        }
    }

    #pragma unroll
    for (int m = 0; m < 10; ++m) {
        int s = ty + 16*m;
        if (s >= cS) continue;
        float al = 0.f;
        #pragma unroll
        for (int n = 0; n < 4; ++n) {
            int c2 = c2base + tx + 16*n;
            float x2v = (img[(b*cS + s)*cC + c2] + sTk[c2])*sS2[c2];
            al += acc[m][n]*x2v;
        }
        atomicAdd(&g_A[(z*cB + b)*MPAD + s], al);
    }
}

// ---------------- k_final --------------------------------------------------
__global__ void k_final(const float* __restrict__ W_s2, const float* __restrict__ b_s2,
                        const float* __restrict__ W_out, const float* __restrict__ b_out,
                        float* __restrict__ out)
{
    int tid = threadIdx.x;
    int b = tid >> 5, lane = tid & 31;
    float bpv[5]; float ssum = 0.f;
    #pragma unroll
    for (int i = 0; i < 5; ++i) {
        int s = lane + 32*i;
        float bp = 0.f;
        if (s < cS) {
            float w = W_s2[s], be = b_s2[s];
            float ip = w*w*g_A[b*MPAD + s]
                     + w*be*g_A[(cB + b)*MPAD + s]
                     + be*be*g_A[(2*cB + b)*MPAD + s];
            float sg = (ip > 0.f) ? 1.f : ((ip < 0.f) ? -1.f : 0.f);
            bp = sg*sqrtf(fabsf(ip) + 1e-5f);
        }
        bpv[i] = bp;
        ssum += bp*bp;
    }
    for (int o = 16; o > 0; o >>= 1) ssum += __shfl_xor_sync(0xffffffffu, ssum, o);
    float norm = fmaxf(sqrtf(ssum), 1e-12f);
    float acc = 0.f;
    #pragma unroll
    for (int i = 0; i < 5; ++i) {
        int s = lane + 32*i;
        if (s < cS) acc += bpv[i]*W_out[s];
    }
    for (int o = 16; o > 0; o >>= 1) acc += __shfl_xor_sync(0xffffffffu, acc, o);
    if (lane == 0) out[b] = acc/norm + b_out[0];
}

extern "C" void kernel_launch(void* const* d_in, const int* in_sizes, int n_in,
                              void* d_out, int out_size)
{
    int base = (in_sizes[7] == 1) ? 8 : 7;
    const float* sensor = (const float*)d_in[0];
    const float* img    = (const float*)d_in[1];
    const int*   h1     = (const int*)  d_in[3];
    const int*   h2     = (const int*)  d_in[4];
    const int*   s1     = (const int*)  d_in[5];
    const int*   s2     = (const int*)  d_in[6];
    const float* Wsen   = (const float*)d_in[base+0];
    const float* bsen   = (const float*)d_in[base+1];
    const float* Ws2    = (const float*)d_in[base+2];
    const float* bs2    = (const float*)d_in[base+3];
    const float* Wout   = (const float*)d_in[base+4];
    const float* bout   = (const float*)d_in[base+5];
    const float* tok    = (const float*)d_in[base+6];
    float* out = (float*)d_out;

    static int cfg = 0;
    if (!cfg) {
        cudaFuncSetAttribute(k_conv,     cudaFuncAttributeMaxDynamicSharedMemorySize, CONV_SMEM);
        cudaFuncSetAttribute(k_quad_mma, cudaFuncAttributeMaxDynamicSharedMemorySize, SMEM_Q*4);
        cfg = 1;
    }

    k_prep_se1<<<dim3(cB, cS + 1), 256>>>(img, tok, s1, s2, sensor, Wsen, bsen, h1, h2, bs2);
    k_conv<<<dim3(cB, 8), 256, CONV_SMEM>>>(h2, s2);
    k_conv_bias<<<dim3(cB, 8), 256>>>(h1, h2, s1, s2);
    k_quad_mma<<<dim3(cB, 12), 128, SMEM_Q*4>>>(h1, h2, img, tok, s2);
    k_quad_bias<<<dim3(cB, 12, 2), 256>>>(img, h1, h2, tok, s1, s2);
    k_final<<<1, 1024>>>(Ws2, bs2, Wout, bout, out);
}